// round 3
// baseline (speedup 1.0000x reference)
#include <cuda_runtime.h>
#include <cuda_bf16.h>

typedef unsigned long long u64;

// Path index LUT: [lo*16 + l1*4 + l2] -> weight index (reference ordering).
__device__ const signed char PATH_LUT[64] = {
   0,-1,-1,-1, -1, 1,-1,-1, -1,-1, 2,-1, -1,-1,-1, 3,
  -1, 4,-1,-1,  5,-1, 6,-1, -1, 7,-1, 8, -1,-1, 9,-1,
  -1,-1,10,-1, -1,11,-1,12, 13,-1,14,-1, -1,15,-1,16,
  -1,-1,-1,17, -1,-1,18,-1, -1,19,-1,20, 21,-1,22,-1
};

// Compacted per-launch W: 359 structurally-nonzero terms (value duplicated
// into both f32x2 lanes), padded with zeros to 368.
#define NTERM_CAP 368
__device__ __align__(16) float2 d_Wc[NTERM_CAP];

// ---------------------------------------------------------------------------
// Exact CG machinery (init kernel only)
// ---------------------------------------------------------------------------
__device__ __forceinline__ float fct(int k) {
    const float t[11] = {1.f,1.f,2.f,6.f,24.f,120.f,720.f,5040.f,40320.f,362880.f,3628800.f};
    return t[k];
}

__device__ float su2cg(int j1,int m1,int j2,int m2,int j3,int m3) {
    if (m1 + m2 != m3) return 0.f;
    if (m3 > j3 || m3 < -j3) return 0.f;
    int vmin = -j1 + j2 + m3; if (-j1 + m1 > vmin) vmin = -j1 + m1; if (vmin < 0) vmin = 0;
    int vmax = j2 + j3 + m1; if (j3 - j1 + j2 < vmax) vmax = j3 - j1 + j2; if (j3 + m3 < vmax) vmax = j3 + m3;
    if (vmax < vmin) return 0.f;
    float C = (float)(2*j3+1)
            * (fct(j3+j1-j2)*fct(j3-j1+j2)*fct(j1+j2-j3)*fct(j3+m3)*fct(j3-m3))
            / (fct(j1+j2+j3+1)*fct(j1-m1)*fct(j1+m1)*fct(j2-m2)*fct(j2+m2));
    float S = 0.f;
    for (int v = vmin; v <= vmax; ++v) {
        float term = (fct(j2+j3+m1-v)*fct(j1-m1+v))
                   / (fct(v)*fct(j3-j1+j2-v)*fct(j3+m3-v)*fct(v+j1-j2-m3));
        S += (((v + j2 + m2) & 1) ? -term : term);
    }
    return sqrtf(C) * S;
}

struct cf { float r, i; };
__device__ __forceinline__ cf cmul(cf a, cf b) {
    cf o; o.r = a.r*b.r - a.i*b.i; o.i = a.r*b.i + a.i*b.r; return o;
}

// Q[l+mu][l+m] of real->complex basis change, INCLUDING the (-i)^l phase.
__device__ cf Qent(int l, int mu, int m) {
    const float invs = 0.70710678118654752f;
    cf q;
    if (mu == 0) {
        if (m != 0) { q.r = 0.f; q.i = 0.f; return q; }
        q.r = 1.f; q.i = 0.f;
    } else if (mu < 0) {
        if (m == -mu)     { q.r = invs; q.i = 0.f; }
        else if (m == mu) { q.r = 0.f;  q.i = -invs; }
        else              { q.r = 0.f;  q.i = 0.f; return q; }
    } else {
        if (m == mu)       { q.r = (mu & 1) ? -invs : invs; q.i = 0.f; }
        else if (m == -mu) { q.r = 0.f; q.i = (mu & 1) ? -invs : invs; }
        else               { q.r = 0.f; q.i = 0.f; return q; }
    }
    cf o;
    switch (l & 3) {                       // multiply by (-i)^l
        case 0: o = q; break;
        case 1: o.r =  q.i; o.i = -q.r; break;
        case 2: o.r = -q.r; o.i = -q.i; break;
        default: o.r = -q.i; o.i =  q.r; break;
    }
    return o;
}

__device__ float cg_real(int l1,int m1,int l2,int m2,int l3,int m3) {
    float acc = 0.f;
    int am1 = m1 < 0 ? -m1 : m1;
    int am2 = m2 < 0 ? -m2 : m2;
    for (int s1 = 0; s1 < 2; ++s1) {
        if (am1 == 0 && s1 == 1) continue;
        int mu1 = s1 ? -am1 : am1;
        cf q1 = Qent(l1, mu1, m1);
        for (int s2 = 0; s2 < 2; ++s2) {
            if (am2 == 0 && s2 == 1) continue;
            int mu2 = s2 ? -am2 : am2;
            int mu3 = mu1 + mu2;
            if (mu3 > l3 || mu3 < -l3) continue;
            cf q3 = Qent(l3, mu3, m3);
            if (q3.r == 0.f && q3.i == 0.f) continue;
            q3.i = -q3.i;                  // conjugate
            float cg = su2cg(l1, mu1, l2, mu2, l3, mu3);
            if (cg == 0.f) continue;
            cf t = cmul(cmul(q1, Qent(l2, mu2, m2)), q3);
            acc += t.r * cg;
        }
    }
    return acc;
}

// Structural selection rule (identical in both kernels; same as R2, verified).
__device__ __forceinline__ bool term_ok(int l1,int m1,int l2,int m2,int lo,int m3) {
    if ((l1 + l2 + lo) & 1) return false;
    int dl = l1 - l2; if (dl < 0) dl = -dl;
    if (lo < dl || lo > l1 + l2) return false;
    int am1 = m1 < 0 ? -m1 : m1;
    int am2 = m2 < 0 ? -m2 : m2;
    int am3 = m3 < 0 ? -m3 : m3;
    int s = am1 + am2;
    int d = am1 - am2; if (d < 0) d = -d;
    if (am3 != s && am3 != d) return false;
    if ((((m1 < 0) ? 1 : 0) + ((m2 < 0) ? 1 : 0) + ((m3 < 0) ? 1 : 0)) & 1) return false;
    return true;
}

__device__ __forceinline__ void lm_of(int idx, int& l, int& m) {
    l = (idx >= 9) ? 3 : (idx >= 4) ? 2 : (idx >= 1) ? 1 : 0;
    m = idx - l*l - l;
}

__device__ __forceinline__ int cnt_ab(int a, int b) {
    int l1, m1, l2, m2; lm_of(a, l1, m1); lm_of(b, l2, m2);
    int cnt = 0;
    for (int lo = 0; lo <= 3; ++lo)
        for (int m3 = -lo; m3 <= lo; ++m3)
            if (term_ok(l1, m1, l2, m2, lo, m3)) ++cnt;
    return cnt;
}

// 256 threads: thread t handles (a=t>>4, b=t&15); writes its terms at the
// prefix offset so the array order matches tp_main's unrolled enumeration
// (lexicographic (a,b), then lo ascending, m3 ascending).
__global__ void build_w_kernel(const float* __restrict__ weights) {
    int t = threadIdx.x;
    int a = t >> 4, b = t & 15;
    int base = 0;
    for (int u = 0; u < t; ++u) base += cnt_ab(u >> 4, u & 15);

    int l1, m1, l2, m2; lm_of(a, l1, m1); lm_of(b, l2, m2);
    int k = 0;
    for (int lo = 0; lo <= 3; ++lo)
        for (int m3 = -lo; m3 <= lo; ++m3) {
            if (!term_ok(l1, m1, l2, m2, lo, m3)) continue;
            int p = PATH_LUT[lo*16 + l1*4 + l2];
            float v = 0.f;
            if (p >= 0)
                v = weights[p] * sqrtf((float)(2*lo + 1)) * cg_real(l1, m1, l2, m2, lo, m3);
            d_Wc[base + k] = make_float2(v, v);
            ++k;
        }
    if (t == 255)
        for (int j = base + k; j < NTERM_CAP; ++j) d_Wc[j] = make_float2(0.f, 0.f);
}

// ---------------------------------------------------------------------------
// Main kernel: 2 rows/thread, f32x2 FMA, compacted W, paired LDS.128
// ---------------------------------------------------------------------------
__device__ __forceinline__ u64 pk2(float lo, float hi) {
    u64 r; asm("mov.b64 %0, {%1, %2};" : "=l"(r) : "f"(lo), "f"(hi)); return r;
}
__device__ __forceinline__ void upk2(float& lo, float& hi, u64 v) {
    asm("mov.b64 {%0, %1}, %2;" : "=f"(lo), "=f"(hi) : "l"(v));
}
__device__ __forceinline__ u64 mul2(u64 a, u64 b) {
    u64 r; asm("mul.rn.f32x2 %0, %1, %2;" : "=l"(r) : "l"(a), "l"(b)); return r;
}
__device__ __forceinline__ u64 fma2(u64 a, u64 b, u64 c) {
    u64 r; asm("fma.rn.f32x2 %0, %1, %2, %3;" : "=l"(r) : "l"(a), "l"(b), "l"(c)); return r;
}

__device__ __forceinline__ void load_row(const float* __restrict__ p, int r, int n, float v[16]) {
    if (r < n) {
        const float4* q = (const float4*)p + r * 4;
        #pragma unroll
        for (int i = 0; i < 4; ++i) {
            float4 t = q[i];
            v[4*i] = t.x; v[4*i+1] = t.y; v[4*i+2] = t.z; v[4*i+3] = t.w;
        }
    } else {
        #pragma unroll
        for (int i = 0; i < 16; ++i) v[i] = 0.f;
    }
}

__global__ void __launch_bounds__(128)
tp_main(const float* __restrict__ x1, const float* __restrict__ x2,
        float* __restrict__ out, int n) {
    __shared__ __align__(16) u64 Wc[NTERM_CAP];
    {
        const float4* src = (const float4*)d_Wc;   // NTERM_CAP u64 = 184 float4
        float4* dst = (float4*)Wc;
        dst[threadIdx.x] = src[threadIdx.x];
        if (threadIdx.x < NTERM_CAP/2 - 128)
            dst[threadIdx.x + 128] = src[threadIdx.x + 128];
    }
    __syncthreads();

    const int r0 = blockIdx.x * 256 + threadIdx.x;
    const int r1 = r0 + 128;

    u64 X1[16], X2[16], AC[16];
    {
        float t0[16], t1[16];
        load_row(x1, r0, n, t0); load_row(x1, r1, n, t1);
        #pragma unroll
        for (int i = 0; i < 16; ++i) X1[i] = pk2(t0[i], t1[i]);
        load_row(x2, r0, n, t0); load_row(x2, r1, n, t1);
        #pragma unroll
        for (int i = 0; i < 16; ++i) X2[i] = pk2(t0[i], t1[i]);
    }
    #pragma unroll
    for (int i = 0; i < 16; ++i) AC[i] = 0ull;

    // Compile-time enumeration of the 359 structurally-nonzero terms.
    // tc is a running counter, constant-folded after full unroll; W values
    // are fetched two-at-a-time with 128-bit shared loads.
    int tc = 0;
    u64 wnxt = 0ull;
    #pragma unroll
    for (int l1 = 0; l1 <= 3; ++l1)
    #pragma unroll
    for (int m1 = -3; m1 <= 3; ++m1) {
        if (m1 < -l1 || m1 > l1) continue;
        #pragma unroll
        for (int l2 = 0; l2 <= 3; ++l2)
        #pragma unroll
        for (int m2 = -3; m2 <= 3; ++m2) {
            if (m2 < -l2 || m2 > l2) continue;
            const int a = l1*l1 + l1 + m1;
            const int b = l2*l2 + l2 + m2;
            const u64 pa = mul2(X1[a], X2[b]);   // DCE'd if no term consumes it
            #pragma unroll
            for (int lo = 0; lo <= 3; ++lo)
            #pragma unroll
            for (int m3 = -3; m3 <= 3; ++m3) {
                if (m3 < -lo || m3 > lo) continue;
                if (!term_ok(l1, m1, l2, m2, lo, m3)) continue;
                const int c = lo*lo + lo + m3;
                u64 wcur;
                if ((tc & 1) == 0) {
                    ulonglong2 wv = ((const ulonglong2*)Wc)[tc >> 1];  // LDS.128
                    wcur = wv.x; wnxt = wv.y;
                } else {
                    wcur = wnxt;
                }
                AC[c] = fma2(wcur, pa, AC[c]);
                ++tc;
            }
        }
    }

    // Unpack and store both rows.
    float o0[16], o1[16];
    #pragma unroll
    for (int i = 0; i < 16; ++i) upk2(o0[i], o1[i], AC[i]);
    if (r0 < n) {
        float4* q = (float4*)out + r0 * 4;
        #pragma unroll
        for (int i = 0; i < 4; ++i)
            q[i] = make_float4(o0[4*i], o0[4*i+1], o0[4*i+2], o0[4*i+3]);
    }
    if (r1 < n) {
        float4* q = (float4*)out + r1 * 4;
        #pragma unroll
        for (int i = 0; i < 4; ++i)
            q[i] = make_float4(o1[4*i], o1[4*i+1], o1[4*i+2], o1[4*i+3]);
    }
}

extern "C" void kernel_launch(void* const* d_in, const int* in_sizes, int n_in,
                              void* d_out, int out_size) {
    const float* x1 = (const float*)d_in[0];
    const float* x2 = (const float*)d_in[1];
    const float* weights = (const float*)d_in[2];
    float* out = (float*)d_out;
    const int n = in_sizes[0] / 16;

    build_w_kernel<<<1, 256>>>(weights);
    const int blocks = (n + 255) / 256;
    tp_main<<<blocks, 128>>>(x1, x2, out, n);
}

// round 4
// speedup vs baseline: 2.9079x; 2.9079x over previous
#include <cuda_runtime.h>
#include <cuda_bf16.h>

typedef unsigned long long u64;

// ===========================================================================
// Compile-time CG machinery (all constexpr, double precision)
// ===========================================================================
__host__ __device__ constexpr double cfct(int k) {
    double r = 1.0;
    for (int i = 2; i <= k; ++i) r *= (double)i;
    return r;
}
__host__ __device__ constexpr double csqrt(double x) {
    if (x <= 0.0) return 0.0;
    double g = x < 1.0 ? 1.0 : x;
    for (int i = 0; i < 40; ++i) g = 0.5 * (g + x / g);
    return g;
}
__host__ __device__ constexpr double csu2(int j1,int m1,int j2,int m2,int j3,int m3) {
    if (m1 + m2 != m3) return 0.0;
    if (m3 > j3 || m3 < -j3) return 0.0;
    int vmin = -j1 + j2 + m3; if (-j1 + m1 > vmin) vmin = -j1 + m1; if (vmin < 0) vmin = 0;
    int vmax = j2 + j3 + m1; if (j3 - j1 + j2 < vmax) vmax = j3 - j1 + j2; if (j3 + m3 < vmax) vmax = j3 + m3;
    if (vmax < vmin) return 0.0;
    double C = (2.0*j3 + 1.0)
             * (cfct(j3+j1-j2)*cfct(j3-j1+j2)*cfct(j1+j2-j3)*cfct(j3+m3)*cfct(j3-m3))
             / (cfct(j1+j2+j3+1)*cfct(j1-m1)*cfct(j1+m1)*cfct(j2-m2)*cfct(j2+m2));
    double S = 0.0;
    for (int v = vmin; v <= vmax; ++v) {
        double t = (cfct(j2+j3+m1-v)*cfct(j1-m1+v))
                 / (cfct(v)*cfct(j3-j1+j2-v)*cfct(j3+m3-v)*cfct(v+j1-j2-m3));
        S += (((v + j2 + m2) & 1) ? -t : t);
    }
    return csqrt(C) * S;
}

struct cc { double r, i; };
__host__ __device__ constexpr cc cmulc(cc a, cc b) {
    return cc{a.r*b.r - a.i*b.i, a.r*b.i + a.i*b.r};
}
// Q[l+mu][l+m] of real->complex basis change, INCLUDING the (-i)^l phase.
__host__ __device__ constexpr cc qent(int l, int mu, int m) {
    const double invs = 0.70710678118654752440;
    cc q{0.0, 0.0};
    if (mu == 0) {
        if (m != 0) return cc{0.0, 0.0};
        q = cc{1.0, 0.0};
    } else if (mu < 0) {
        if (m == -mu)      q = cc{invs, 0.0};
        else if (m == mu)  q = cc{0.0, -invs};
        else return cc{0.0, 0.0};
    } else {
        if (m == mu)       q = cc{(mu & 1) ? -invs : invs, 0.0};
        else if (m == -mu) q = cc{0.0, (mu & 1) ? -invs : invs};
        else return cc{0.0, 0.0};
    }
    cc o{0.0, 0.0};
    switch (l & 3) {                       // multiply by (-i)^l
        case 0: o = q; break;
        case 1: o = cc{ q.i, -q.r}; break;
        case 2: o = cc{-q.r, -q.i}; break;
        default: o = cc{-q.i,  q.r}; break;
    }
    return o;
}
__host__ __device__ constexpr double ccgreal(int l1,int m1,int l2,int m2,int l3,int m3) {
    double acc = 0.0;
    int am1 = m1 < 0 ? -m1 : m1;
    int am2 = m2 < 0 ? -m2 : m2;
    for (int s1 = 0; s1 < 2; ++s1) {
        if (am1 == 0 && s1 == 1) continue;
        int mu1 = s1 ? -am1 : am1;
        cc q1 = qent(l1, mu1, m1);
        for (int s2 = 0; s2 < 2; ++s2) {
            if (am2 == 0 && s2 == 1) continue;
            int mu2 = s2 ? -am2 : am2;
            int mu3 = mu1 + mu2;
            if (mu3 > l3 || mu3 < -l3) continue;
            cc q3 = qent(l3, mu3, m3);
            if (q3.r == 0.0 && q3.i == 0.0) continue;
            q3.i = -q3.i;                  // conjugate
            double cg = csu2(l1, mu1, l2, mu2, l3, mu3);
            if (cg == 0.0) continue;
            cc t = cmulc(cmulc(q1, qent(l2, mu2, m2)), q3);
            acc += t.r * cg;
        }
    }
    return acc;
}

// Path index LUT (reference weight ordering), -1 if path absent.
__host__ __device__ constexpr int pathof(int lo, int l1, int l2) {
    const signed char L[64] = {
       0,-1,-1,-1, -1, 1,-1,-1, -1,-1, 2,-1, -1,-1,-1, 3,
      -1, 4,-1,-1,  5,-1, 6,-1, -1, 7,-1, 8, -1,-1, 9,-1,
      -1,-1,10,-1, -1,11,-1,12, 13,-1,14,-1, -1,15,-1,16,
      -1,-1,-1,17, -1,-1,18,-1, -1,19,-1,20, 21,-1,22,-1
    };
    return L[lo*16 + l1*4 + l2];
}

// Structural selection rule (validated R2/R3 at rel_err 1.3e-7).
__host__ __device__ constexpr bool term_ok(int l1,int m1,int l2,int m2,int lo,int m3) {
    if ((l1 + l2 + lo) & 1) return false;
    int dl = l1 - l2; if (dl < 0) dl = -dl;
    if (lo < dl || lo > l1 + l2) return false;
    int am1 = m1 < 0 ? -m1 : m1;
    int am2 = m2 < 0 ? -m2 : m2;
    int am3 = m3 < 0 ? -m3 : m3;
    int s = am1 + am2;
    int d = am1 - am2; if (d < 0) d = -d;
    if (am3 != s && am3 != d) return false;
    if ((((m1 < 0) ? 1 : 0) + ((m2 < 0) ? 1 : 0) + ((m3 < 0) ? 1 : 0)) & 1) return false;
    return true;
}

// CG table: v[(a*16+b)*16+c] = sqrt(2lo+1) * CG_real(l1,m1,l2,m2,lo,m3)
struct CGT { float v[4096]; };
__host__ __device__ constexpr CGT make_cgt() {
    CGT t{};
    for (int a = 0; a < 16; ++a)
    for (int b = 0; b < 16; ++b)
    for (int c = 0; c < 16; ++c) {
        int l1 = (a >= 9) ? 3 : (a >= 4) ? 2 : (a >= 1) ? 1 : 0;
        int l2 = (b >= 9) ? 3 : (b >= 4) ? 2 : (b >= 1) ? 1 : 0;
        int lo = (c >= 9) ? 3 : (c >= 4) ? 2 : (c >= 1) ? 1 : 0;
        int m1 = a - l1*l1 - l1;
        int m2 = b - l2*l2 - l2;
        int m3 = c - lo*lo - lo;
        double val = 0.0;
        if (pathof(lo, l1, l2) >= 0 && term_ok(l1, m1, l2, m2, lo, m3))
            val = csqrt(2.0*lo + 1.0) * ccgreal(l1, m1, l2, m2, lo, m3);
        t.v[(a*16 + b)*16 + c] = (float)val;
    }
    return t;
}

// ===========================================================================
// Packed f32x2 helpers
// ===========================================================================
__device__ __forceinline__ u64 pk2(float lo, float hi) {
    u64 r; asm("mov.b64 %0, {%1, %2};" : "=l"(r) : "f"(lo), "f"(hi)); return r;
}
__device__ __forceinline__ void upk2(float& lo, float& hi, u64 v) {
    asm("mov.b64 {%0, %1}, %2;" : "=f"(lo), "=f"(hi) : "l"(v));
}
__device__ __forceinline__ u64 mul2(u64 a, u64 b) {
    u64 r; asm("mul.rn.f32x2 %0, %1, %2;" : "=l"(r) : "l"(a), "l"(b)); return r;
}
__device__ __forceinline__ u64 fma2(u64 a, u64 b, u64 c) {
    u64 r; asm("fma.rn.f32x2 %0, %1, %2, %3;" : "=l"(r) : "l"(a), "l"(b), "l"(c)); return r;
}

__device__ __forceinline__ void load_row(const float* __restrict__ p, int r, int n, float v[16]) {
    if (r < n) {
        const float4* q = (const float4*)p + r * 4;
        #pragma unroll
        for (int i = 0; i < 4; ++i) {
            float4 t = q[i];
            v[4*i] = t.x; v[4*i+1] = t.y; v[4*i+2] = t.z; v[4*i+3] = t.w;
        }
    } else {
        #pragma unroll
        for (int i = 0; i < 16; ++i) v[i] = 0.f;
    }
}

// ===========================================================================
// Main (and only) kernel: 2 rows/thread, f32x2, CG as compile-time constants
// ===========================================================================
__global__ void __launch_bounds__(128)
tp_main(const float* __restrict__ x1, const float* __restrict__ x2,
        const float* __restrict__ weights, float* __restrict__ out, int n) {
    // Compile-time constant table; loads with constant indices fold to imms.
    static constexpr CGT CG = make_cgt();

    const int r0 = blockIdx.x * 256 + threadIdx.x;
    const int r1 = r0 + 128;

    float wreg[23];
    #pragma unroll
    for (int p = 0; p < 23; ++p) wreg[p] = __ldg(weights + p);

    u64 X1[16], X2[16], AC[16];
    {
        float t0[16], t1[16];
        load_row(x1, r0, n, t0); load_row(x1, r1, n, t1);
        #pragma unroll
        for (int i = 0; i < 16; ++i) X1[i] = pk2(t0[i], t1[i]);
        load_row(x2, r0, n, t0); load_row(x2, r1, n, t1);
        #pragma unroll
        for (int i = 0; i < 16; ++i) X2[i] = pk2(t0[i], t1[i]);
    }
    #pragma unroll
    for (int i = 0; i < 16; ++i) AC[i] = 0ull;

    // Path-major contraction: t[m3] += cg * (x1[a]*x2[b]); AC[c] += w_p * t.
    #pragma unroll
    for (int l1 = 0; l1 <= 3; ++l1)
    #pragma unroll
    for (int l2 = 0; l2 <= 3; ++l2)
    #pragma unroll
    for (int lo = 0; lo <= 3; ++lo) {
        if ((l1 + l2 + lo) & 1) continue;
        {
            const int dl = l1 > l2 ? l1 - l2 : l2 - l1;
            if (lo < dl || lo > l1 + l2) continue;
        }
        const int p = pathof(lo, l1, l2);
        if (p < 0) continue;

        u64 t[7];
        #pragma unroll
        for (int i = 0; i < 7; ++i) t[i] = 0ull;

        #pragma unroll
        for (int m1 = -3; m1 <= 3; ++m1) {
            if (m1 < -l1 || m1 > l1) continue;
            #pragma unroll
            for (int m2 = -3; m2 <= 3; ++m2) {
                if (m2 < -l2 || m2 > l2) continue;
                #pragma unroll
                for (int m3 = -3; m3 <= 3; ++m3) {
                    if (m3 < -lo || m3 > lo) continue;
                    if (!term_ok(l1, m1, l2, m2, lo, m3)) continue;
                    const int a = l1*l1 + l1 + m1;
                    const int b = l2*l2 + l2 + m2;
                    const int c = lo*lo + lo + m3;
                    const float cg = CG.v[(a*16 + b)*16 + c]; // folds to imm
                    if (cg == 0.f) continue;                  // folded branch
                    const u64 pa = mul2(X1[a], X2[b]);        // CSE'd across lo
                    t[lo + m3] = fma2(pk2(cg, cg), pa, t[lo + m3]);
                }
            }
        }
        const u64 w2 = pk2(wreg[p], wreg[p]);
        #pragma unroll
        for (int m3 = -lo; m3 <= lo; ++m3) {
            const int c = lo*lo + lo + m3;
            AC[c] = fma2(w2, t[lo + m3], AC[c]);
        }
    }

    // Unpack and store both rows.
    float o0[16], o1[16];
    #pragma unroll
    for (int i = 0; i < 16; ++i) upk2(o0[i], o1[i], AC[i]);
    if (r0 < n) {
        float4* q = (float4*)out + r0 * 4;
        #pragma unroll
        for (int i = 0; i < 4; ++i)
            q[i] = make_float4(o0[4*i], o0[4*i+1], o0[4*i+2], o0[4*i+3]);
    }
    if (r1 < n) {
        float4* q = (float4*)out + r1 * 4;
        #pragma unroll
        for (int i = 0; i < 4; ++i)
            q[i] = make_float4(o1[4*i], o1[4*i+1], o1[4*i+2], o1[4*i+3]);
    }
}

extern "C" void kernel_launch(void* const* d_in, const int* in_sizes, int n_in,
                              void* d_out, int out_size) {
    const float* x1 = (const float*)d_in[0];
    const float* x2 = (const float*)d_in[1];
    const float* weights = (const float*)d_in[2];
    float* out = (float*)d_out;
    const int n = in_sizes[0] / 16;

    const int blocks = (n + 255) / 256;
    tp_main<<<blocks, 128>>>(x1, x2, weights, out, n);
}

// round 5
// speedup vs baseline: 3.0868x; 1.0615x over previous
#include <cuda_runtime.h>
#include <cuda_bf16.h>

typedef unsigned long long u64;

// ===========================================================================
// Compile-time CG machinery (all constexpr, double precision)
// ===========================================================================
__host__ __device__ constexpr double cfct(int k) {
    double r = 1.0;
    for (int i = 2; i <= k; ++i) r *= (double)i;
    return r;
}
__host__ __device__ constexpr double csqrt(double x) {
    if (x <= 0.0) return 0.0;
    double g = x < 1.0 ? 1.0 : x;
    for (int i = 0; i < 40; ++i) g = 0.5 * (g + x / g);
    return g;
}
__host__ __device__ constexpr double csu2(int j1,int m1,int j2,int m2,int j3,int m3) {
    if (m1 + m2 != m3) return 0.0;
    if (m3 > j3 || m3 < -j3) return 0.0;
    int vmin = -j1 + j2 + m3; if (-j1 + m1 > vmin) vmin = -j1 + m1; if (vmin < 0) vmin = 0;
    int vmax = j2 + j3 + m1; if (j3 - j1 + j2 < vmax) vmax = j3 - j1 + j2; if (j3 + m3 < vmax) vmax = j3 + m3;
    if (vmax < vmin) return 0.0;
    double C = (2.0*j3 + 1.0)
             * (cfct(j3+j1-j2)*cfct(j3-j1+j2)*cfct(j1+j2-j3)*cfct(j3+m3)*cfct(j3-m3))
             / (cfct(j1+j2+j3+1)*cfct(j1-m1)*cfct(j1+m1)*cfct(j2-m2)*cfct(j2+m2));
    double S = 0.0;
    for (int v = vmin; v <= vmax; ++v) {
        double t = (cfct(j2+j3+m1-v)*cfct(j1-m1+v))
                 / (cfct(v)*cfct(j3-j1+j2-v)*cfct(j3+m3-v)*cfct(v+j1-j2-m3));
        S += (((v + j2 + m2) & 1) ? -t : t);
    }
    return csqrt(C) * S;
}

struct cc { double r, i; };
__host__ __device__ constexpr cc cmulc(cc a, cc b) {
    return cc{a.r*b.r - a.i*b.i, a.r*b.i + a.i*b.r};
}
__host__ __device__ constexpr cc qent(int l, int mu, int m) {
    const double invs = 0.70710678118654752440;
    cc q{0.0, 0.0};
    if (mu == 0) {
        if (m != 0) return cc{0.0, 0.0};
        q = cc{1.0, 0.0};
    } else if (mu < 0) {
        if (m == -mu)      q = cc{invs, 0.0};
        else if (m == mu)  q = cc{0.0, -invs};
        else return cc{0.0, 0.0};
    } else {
        if (m == mu)       q = cc{(mu & 1) ? -invs : invs, 0.0};
        else if (m == -mu) q = cc{0.0, (mu & 1) ? -invs : invs};
        else return cc{0.0, 0.0};
    }
    cc o{0.0, 0.0};
    switch (l & 3) {
        case 0: o = q; break;
        case 1: o = cc{ q.i, -q.r}; break;
        case 2: o = cc{-q.r, -q.i}; break;
        default: o = cc{-q.i,  q.r}; break;
    }
    return o;
}
__host__ __device__ constexpr double ccgreal(int l1,int m1,int l2,int m2,int l3,int m3) {
    double acc = 0.0;
    int am1 = m1 < 0 ? -m1 : m1;
    int am2 = m2 < 0 ? -m2 : m2;
    for (int s1 = 0; s1 < 2; ++s1) {
        if (am1 == 0 && s1 == 1) continue;
        int mu1 = s1 ? -am1 : am1;
        cc q1 = qent(l1, mu1, m1);
        for (int s2 = 0; s2 < 2; ++s2) {
            if (am2 == 0 && s2 == 1) continue;
            int mu2 = s2 ? -am2 : am2;
            int mu3 = mu1 + mu2;
            if (mu3 > l3 || mu3 < -l3) continue;
            cc q3 = qent(l3, mu3, m3);
            if (q3.r == 0.0 && q3.i == 0.0) continue;
            q3.i = -q3.i;
            double cg = csu2(l1, mu1, l2, mu2, l3, mu3);
            if (cg == 0.0) continue;
            cc t = cmulc(cmulc(q1, qent(l2, mu2, m2)), q3);
            acc += t.r * cg;
        }
    }
    return acc;
}

__host__ __device__ constexpr int pathof(int lo, int l1, int l2) {
    const signed char L[64] = {
       0,-1,-1,-1, -1, 1,-1,-1, -1,-1, 2,-1, -1,-1,-1, 3,
      -1, 4,-1,-1,  5,-1, 6,-1, -1, 7,-1, 8, -1,-1, 9,-1,
      -1,-1,10,-1, -1,11,-1,12, 13,-1,14,-1, -1,15,-1,16,
      -1,-1,-1,17, -1,-1,18,-1, -1,19,-1,20, 21,-1,22,-1
    };
    return L[lo*16 + l1*4 + l2];
}

__host__ __device__ constexpr bool term_ok(int l1,int m1,int l2,int m2,int lo,int m3) {
    if ((l1 + l2 + lo) & 1) return false;
    int dl = l1 - l2; if (dl < 0) dl = -dl;
    if (lo < dl || lo > l1 + l2) return false;
    int am1 = m1 < 0 ? -m1 : m1;
    int am2 = m2 < 0 ? -m2 : m2;
    int am3 = m3 < 0 ? -m3 : m3;
    int s = am1 + am2;
    int d = am1 - am2; if (d < 0) d = -d;
    if (am3 != s && am3 != d) return false;
    if ((((m1 < 0) ? 1 : 0) + ((m2 < 0) ? 1 : 0) + ((m3 < 0) ? 1 : 0)) & 1) return false;
    return true;
}

struct CGT { float v[4096]; };
__host__ __device__ constexpr CGT make_cgt() {
    CGT t{};
    for (int a = 0; a < 16; ++a)
    for (int b = 0; b < 16; ++b)
    for (int c = 0; c < 16; ++c) {
        int l1 = (a >= 9) ? 3 : (a >= 4) ? 2 : (a >= 1) ? 1 : 0;
        int l2 = (b >= 9) ? 3 : (b >= 4) ? 2 : (b >= 1) ? 1 : 0;
        int lo = (c >= 9) ? 3 : (c >= 4) ? 2 : (c >= 1) ? 1 : 0;
        int m1 = a - l1*l1 - l1;
        int m2 = b - l2*l2 - l2;
        int m3 = c - lo*lo - lo;
        double val = 0.0;
        if (pathof(lo, l1, l2) >= 0 && term_ok(l1, m1, l2, m2, lo, m3))
            val = csqrt(2.0*lo + 1.0) * ccgreal(l1, m1, l2, m2, lo, m3);
        t.v[(a*16 + b)*16 + c] = (float)val;
    }
    return t;
}

// ===========================================================================
// Packed f32x2 helpers
// ===========================================================================
__device__ __forceinline__ u64 pk2(float lo, float hi) {
    u64 r; asm("mov.b64 %0, {%1, %2};" : "=l"(r) : "f"(lo), "f"(hi)); return r;
}
__device__ __forceinline__ void upk2(float& lo, float& hi, u64 v) {
    asm("mov.b64 {%0, %1}, %2;" : "=f"(lo), "=f"(hi) : "l"(v));
}
__device__ __forceinline__ u64 mul2(u64 a, u64 b) {
    u64 r; asm("mul.rn.f32x2 %0, %1, %2;" : "=l"(r) : "l"(a), "l"(b)); return r;
}
__device__ __forceinline__ u64 fma2(u64 a, u64 b, u64 c) {
    u64 r; asm("fma.rn.f32x2 %0, %1, %2, %3;" : "=l"(r) : "l"(a), "l"(b), "l"(c)); return r;
}

__device__ __forceinline__ void load_row(const float* __restrict__ p, int r, int n, float v[16]) {
    if (r < n) {
        const float4* q = (const float4*)p + r * 4;
        #pragma unroll
        for (int i = 0; i < 4; ++i) {
            float4 t = q[i];
            v[4*i] = t.x; v[4*i+1] = t.y; v[4*i+2] = t.z; v[4*i+3] = t.w;
        }
    } else {
        #pragma unroll
        for (int i = 0; i < 16; ++i) v[i] = 0.f;
    }
}

// ===========================================================================
// Main kernel: 2 rows/thread, f32x2, compile-time CG constants.
// launch_bounds(128, 4): cap regs at 128 -> 4 blocks/SM (occupancy push).
// ===========================================================================
__global__ void __launch_bounds__(128, 4)
tp_main(const float* __restrict__ x1, const float* __restrict__ x2,
        const float* __restrict__ weights, float* __restrict__ out, int n) {
    static constexpr CGT CG = make_cgt();

    const int r0 = blockIdx.x * 256 + threadIdx.x;
    const int r1 = r0 + 128;

    u64 X1[16], X2[16], AC[16];
    {
        float t0[16], t1[16];
        load_row(x1, r0, n, t0); load_row(x1, r1, n, t1);
        #pragma unroll
        for (int i = 0; i < 16; ++i) X1[i] = pk2(t0[i], t1[i]);
        load_row(x2, r0, n, t0); load_row(x2, r1, n, t1);
        #pragma unroll
        for (int i = 0; i < 16; ++i) X2[i] = pk2(t0[i], t1[i]);
    }
    #pragma unroll
    for (int i = 0; i < 16; ++i) AC[i] = 0ull;

    // Path-major: t[m3] += cg * (x1[a]*x2[b]); then AC[c] += w_p * t[m3].
    // Weight loaded on demand (uniform LDG, L1-resident) to save registers.
    #pragma unroll
    for (int l1 = 0; l1 <= 3; ++l1)
    #pragma unroll
    for (int l2 = 0; l2 <= 3; ++l2)
    #pragma unroll
    for (int lo = 0; lo <= 3; ++lo) {
        if ((l1 + l2 + lo) & 1) continue;
        {
            const int dl = l1 > l2 ? l1 - l2 : l2 - l1;
            if (lo < dl || lo > l1 + l2) continue;
        }
        const int p = pathof(lo, l1, l2);
        if (p < 0) continue;

        u64 t[7];
        #pragma unroll
        for (int i = 0; i < 7; ++i) t[i] = 0ull;

        #pragma unroll
        for (int m1 = -3; m1 <= 3; ++m1) {
            if (m1 < -l1 || m1 > l1) continue;
            #pragma unroll
            for (int m2 = -3; m2 <= 3; ++m2) {
                if (m2 < -l2 || m2 > l2) continue;
                #pragma unroll
                for (int m3 = -3; m3 <= 3; ++m3) {
                    if (m3 < -lo || m3 > lo) continue;
                    if (!term_ok(l1, m1, l2, m2, lo, m3)) continue;
                    const int a = l1*l1 + l1 + m1;
                    const int b = l2*l2 + l2 + m2;
                    const int c = lo*lo + lo + m3;
                    const float cg = CG.v[(a*16 + b)*16 + c]; // folds to imm
                    if (cg == 0.f) continue;
                    const u64 pa = mul2(X1[a], X2[b]);        // CSE'd across lo
                    t[lo + m3] = fma2(pk2(cg, cg), pa, t[lo + m3]);
                }
            }
        }
        const float wp = __ldg(weights + p);
        const u64 w2 = pk2(wp, wp);
        #pragma unroll
        for (int m3 = -lo; m3 <= lo; ++m3) {
            const int c = lo*lo + lo + m3;
            AC[c] = fma2(w2, t[lo + m3], AC[c]);
        }
    }

    float o0[16], o1[16];
    #pragma unroll
    for (int i = 0; i < 16; ++i) upk2(o0[i], o1[i], AC[i]);
    if (r0 < n) {
        float4* q = (float4*)out + r0 * 4;
        #pragma unroll
        for (int i = 0; i < 4; ++i)
            q[i] = make_float4(o0[4*i], o0[4*i+1], o0[4*i+2], o0[4*i+3]);
    }
    if (r1 < n) {
        float4* q = (float4*)out + r1 * 4;
        #pragma unroll
        for (int i = 0; i < 4; ++i)
            q[i] = make_float4(o1[4*i], o1[4*i+1], o1[4*i+2], o1[4*i+3]);
    }
}

extern "C" void kernel_launch(void* const* d_in, const int* in_sizes, int n_in,
                              void* d_out, int out_size) {
    const float* x1 = (const float*)d_in[0];
    const float* x2 = (const float*)d_in[1];
    const float* weights = (const float*)d_in[2];
    float* out = (float*)d_out;
    const int n = in_sizes[0] / 16;

    const int blocks = (n + 255) / 256;
    tp_main<<<blocks, 128>>>(x1, x2, weights, out, n);
}